// round 1
// baseline (speedup 1.0000x reference)
#include <cuda_runtime.h>
#include <cuda_fp16.h>
#include <cstdint>

#define BATCH 4
#define SEQ   2048
#define DIN   2048
#define DOUT  2048
#define MTOT  (BATCH * SEQ)   // 8192 tokens
#define GROUP 32
#define NGROUP (DIN / GROUP)  // 64

// Scratch (allocation-free rule: __device__ globals)
__device__ __half g_A[(size_t)MTOT * DIN];   // 32 MB: exact integer (q - zp) per token
__device__ __half g_W[(size_t)DOUT * DIN];   // 8 MB : dequantized weights
__device__ float  g_sx[MTOT];                // per-token activation scale

// ---------------------------------------------------------------------------
// Kernel 1: per-token asymmetric int8 fake-quant of x.
// Stores (q - zp) (integer in [-255,255], EXACT in fp16) and scale separately.
// ---------------------------------------------------------------------------
__global__ void quant_x_kernel(const float* __restrict__ x) {
    const int token = blockIdx.x;
    const float* xr = x + (size_t)token * DIN;
    __half* ar = g_A + (size_t)token * DIN;
    const int tid = threadIdx.x;  // 256 threads, 8 elems each

    float v[8];
    float vmin = 0.0f, vmax = 0.0f;  // reference clamps min<=0, max>=0
#pragma unroll
    for (int i = 0; i < 8; i++) {
        v[i] = xr[tid + i * 256];
        vmin = fminf(vmin, v[i]);
        vmax = fmaxf(vmax, v[i]);
    }
#pragma unroll
    for (int off = 16; off > 0; off >>= 1) {
        vmin = fminf(vmin, __shfl_xor_sync(0xffffffffu, vmin, off));
        vmax = fmaxf(vmax, __shfl_xor_sync(0xffffffffu, vmax, off));
    }
    __shared__ float smin[8], smax[8];
    if ((tid & 31) == 0) { smin[tid >> 5] = vmin; smax[tid >> 5] = vmax; }
    __syncthreads();
    float bmin = smin[0], bmax = smax[0];
#pragma unroll
    for (int i = 1; i < 8; i++) { bmin = fminf(bmin, smin[i]); bmax = fmaxf(bmax, smax[i]); }

    float scale = (bmax - bmin) / 255.0f;
    scale = fmaxf(scale, 1.1920928955078125e-07f);  // jnp.finfo(f32).eps
    float zp = fminf(fmaxf(-128.0f - rintf(bmin / scale), -128.0f), 127.0f);
    if (tid == 0) g_sx[token] = scale;

#pragma unroll
    for (int i = 0; i < 8; i++) {
        float q = fminf(fmaxf(rintf(v[i] / scale) + zp, -128.0f), 127.0f);
        ar[tid + i * 256] = __float2half_rn(q - zp);  // exact integer in fp16
    }
}

// ---------------------------------------------------------------------------
// Kernel 2: int4 grouped weight dequant -> fp16
// ---------------------------------------------------------------------------
__global__ void wdq_kernel(const int4* __restrict__ w_int,
                           const float* __restrict__ ws,
                           const float* __restrict__ wz) {
    const int idx = blockIdx.x * 256 + threadIdx.x;  // over DOUT*DIN/4
    int4 w = w_int[idx];
    const int k4 = idx & (DIN / 4 - 1);
    const int o  = idx / (DIN / 4);
    const int g  = (k4 * 4) / GROUP;
    const float s = ws[o * NGROUP + g];
    const float z = wz[o * NGROUP + g];
    __half2 lo = __floats2half2_rn(((float)w.x - z) * s, ((float)w.y - z) * s);
    __half2 hi = __floats2half2_rn(((float)w.z - z) * s, ((float)w.w - z) * s);
    __half2* dst = (__half2*)g_W + (size_t)idx * 2;
    dst[0] = lo;
    dst[1] = hi;
}

// ---------------------------------------------------------------------------
// Kernel 3: GEMM  out[m,n] = s_x[m] * sum_k A[m,k] * W[n,k]
// 128x128x32 block tile, 8 warps (2x4), warp tile 64x32, cp.async 2-stage,
// ldmatrix + mma.sync.m16n8k16 f16 -> f32.
// ---------------------------------------------------------------------------
#define BM 128
#define BN 128
#define BK 32
#define LDS_PITCH 40  // 32 + 8-half pad: conflict-free ldmatrix (80B row stride)

__device__ __forceinline__ void cp_async16(uint32_t saddr, const void* gaddr) {
    asm volatile("cp.async.cg.shared.global [%0], [%1], 16;\n" :: "r"(saddr), "l"(gaddr));
}
__device__ __forceinline__ void cp_commit() { asm volatile("cp.async.commit_group;\n" ::: "memory"); }
__device__ __forceinline__ void cp_wait0()  { asm volatile("cp.async.wait_group 0;\n" ::: "memory"); }

__device__ __forceinline__ void prefetch_tile(
    const __half* Ag, const __half* Wg,
    uint32_t sA, uint32_t sB, uint32_t stage_bytes,
    int kt, int buf, int row0, int row1, int col0)
{
    const size_t goff0 = (size_t)row0 * DIN + kt * BK + col0;
    const size_t goff1 = (size_t)row1 * DIN + kt * BK + col0;
    const uint32_t so0 = (uint32_t)(row0 * LDS_PITCH + col0) * 2 + buf * stage_bytes;
    const uint32_t so1 = (uint32_t)(row1 * LDS_PITCH + col0) * 2 + buf * stage_bytes;
    cp_async16(sA + so0, Ag + goff0);
    cp_async16(sA + so1, Ag + goff1);
    cp_async16(sB + so0, Wg + goff0);
    cp_async16(sB + so1, Wg + goff1);
    cp_commit();
}

__global__ void gemm_kernel(float* __restrict__ out) {
    __shared__ __align__(16) __half As[2][BM][LDS_PITCH];
    __shared__ __align__(16) __half Bs[2][BN][LDS_PITCH];

    const int tid  = threadIdx.x;      // 256
    const int lane = tid & 31;
    const int wid  = tid >> 5;
    const int warp_m = wid >> 2;       // 0..1  -> 64 rows
    const int warp_n = wid & 3;        // 0..3  -> 32 cols
    const int bm = blockIdx.y, bn = blockIdx.x;

    const __half* Ag = g_A + (size_t)bm * BM * DIN;
    const __half* Wg = g_W + (size_t)bn * BN * DIN;

    // cp.async chunk mapping: 512 16B-chunks per tile, 2 per thread
    const int row0 = tid >> 2;
    const int row1 = (tid + 256) >> 2;
    const int col0 = (tid & 3) * 8;  // halves

    const uint32_t sA = (uint32_t)__cvta_generic_to_shared(&As[0][0][0]);
    const uint32_t sB = (uint32_t)__cvta_generic_to_shared(&Bs[0][0][0]);
    const uint32_t stage_bytes = BM * LDS_PITCH * 2;  // 10240

    float acc[4][4][4];
#pragma unroll
    for (int i = 0; i < 4; i++)
#pragma unroll
        for (int j = 0; j < 4; j++)
#pragma unroll
            for (int r = 0; r < 4; r++) acc[i][j][r] = 0.0f;

    // ldmatrix per-lane offsets (within tile)
    const int a_row = warp_m * 64 + (lane & 15);
    const int a_col = (lane >> 4) * 8;
    const int b_row = warp_n * 32 + (lane & 7) + ((lane >> 4) & 1) * 8;
    const int b_col = ((lane >> 3) & 1) * 8;

    prefetch_tile(Ag, Wg, sA, sB, stage_bytes, 0, 0, row0, row1, col0);

    const int NKT = DIN / BK;  // 64
#pragma unroll 1
    for (int kt = 0; kt < NKT; kt++) {
        cp_wait0();
        __syncthreads();
        if (kt + 1 < NKT)
            prefetch_tile(Ag, Wg, sA, sB, stage_bytes, kt + 1, (kt + 1) & 1, row0, row1, col0);

        const int buf = kt & 1;
        const uint32_t aBase = sA + buf * stage_bytes;
        const uint32_t bBase = sB + buf * stage_bytes;

#pragma unroll
        for (int ks = 0; ks < 2; ks++) {
            uint32_t af[4][4];
#pragma unroll
            for (int mt = 0; mt < 4; mt++) {
                uint32_t addr = aBase +
                    (uint32_t)(((a_row + mt * 16) * LDS_PITCH) + ks * 16 + a_col) * 2;
                asm volatile(
                    "ldmatrix.sync.aligned.m8n8.x4.shared.b16 {%0,%1,%2,%3}, [%4];"
                    : "=r"(af[mt][0]), "=r"(af[mt][1]), "=r"(af[mt][2]), "=r"(af[mt][3])
                    : "r"(addr));
            }
            uint32_t bf[4][2];
#pragma unroll
            for (int p = 0; p < 2; p++) {
                uint32_t addr = bBase +
                    (uint32_t)(((b_row + p * 16) * LDS_PITCH) + ks * 16 + b_col) * 2;
                uint32_t r0, r1, r2, r3;
                asm volatile(
                    "ldmatrix.sync.aligned.m8n8.x4.shared.b16 {%0,%1,%2,%3}, [%4];"
                    : "=r"(r0), "=r"(r1), "=r"(r2), "=r"(r3)
                    : "r"(addr));
                bf[2 * p][0] = r0; bf[2 * p][1] = r1;
                bf[2 * p + 1][0] = r2; bf[2 * p + 1][1] = r3;
            }
#pragma unroll
            for (int mt = 0; mt < 4; mt++)
#pragma unroll
                for (int nt = 0; nt < 4; nt++)
                    asm volatile(
                        "mma.sync.aligned.m16n8k16.row.col.f32.f16.f16.f32 "
                        "{%0,%1,%2,%3}, {%4,%5,%6,%7}, {%8,%9}, {%0,%1,%2,%3};"
                        : "+f"(acc[mt][nt][0]), "+f"(acc[mt][nt][1]),
                          "+f"(acc[mt][nt][2]), "+f"(acc[mt][nt][3])
                        : "r"(af[mt][0]), "r"(af[mt][1]), "r"(af[mt][2]), "r"(af[mt][3]),
                          "r"(bf[nt][0]), "r"(bf[nt][1]));
        }
    }

    // Epilogue: scale rows by s_x and store fp32
    const int gm0 = bm * BM + warp_m * 64 + (lane >> 2);
    const int gn0 = bn * BN + warp_n * 32 + (lane & 3) * 2;
#pragma unroll
    for (int mt = 0; mt < 4; mt++) {
        const int r0 = gm0 + mt * 16;
        const float s0 = g_sx[r0];
        const float s1 = g_sx[r0 + 8];
#pragma unroll
        for (int nt = 0; nt < 4; nt++) {
            const int c = gn0 + nt * 8;
            float2 v0 = make_float2(acc[mt][nt][0] * s0, acc[mt][nt][1] * s0);
            float2 v1 = make_float2(acc[mt][nt][2] * s1, acc[mt][nt][3] * s1);
            *(float2*)&out[(size_t)r0 * DOUT + c] = v0;
            *(float2*)&out[(size_t)(r0 + 8) * DOUT + c] = v1;
        }
    }
}

// ---------------------------------------------------------------------------
extern "C" void kernel_launch(void* const* d_in, const int* in_sizes, int n_in,
                              void* d_out, int out_size) {
    (void)in_sizes; (void)n_in; (void)out_size;
    const float* x      = (const float*)d_in[0];
    const int*   w_int  = (const int*)d_in[1];
    const float* w_sc   = (const float*)d_in[2];
    const float* w_zp   = (const float*)d_in[3];
    float* out = (float*)d_out;

    quant_x_kernel<<<MTOT, 256>>>(x);
    wdq_kernel<<<(DOUT * DIN / 4) / 256, 256>>>((const int4*)w_int, w_sc, w_zp);
    gemm_kernel<<<dim3(DOUT / BN, MTOT / BM), 256>>>(out);
}